// round 13
// baseline (speedup 1.0000x reference)
#include <cuda_runtime.h>
#include <cuda_fp16.h>

// Problem constants
#define N_   8
#define C_   64
#define H_   256
#define W_   256
#define HO_  256
#define WO_  256
#define HW_  (H_ * W_)

// NHWC fp16 scratch for all images (67 MB, mostly L2-resident thanks to
// streaming hints on x/out). No allocation.
__device__ __half g_xt[(size_t)N_ * HW_ * C_];

static __device__ __forceinline__ unsigned int h2_as_u(__half2 h) {
    return *reinterpret_cast<unsigned int*>(&h);
}
static __device__ __forceinline__ __half2 u_as_h2(unsigned int u) {
    return *reinterpret_cast<__half2*>(&u);
}

// -------------------------------------------------------------------------
// Kernel 1: NCHW fp32 -> NHWC fp16. (R6 body — proven, near DRAM roofline)
// -------------------------------------------------------------------------
__global__ __launch_bounds__(256) void nchw_to_nhwc_h(const float* __restrict__ x) {
    __shared__ unsigned int smw[64 * 64];   // [ch][pixpair] 16KB

    const int n   = blockIdx.y;
    const int s0  = blockIdx.x * 128;
    const float* xin = x + (size_t)n * (C_ * HW_);
    const int tid  = threadIdx.x;
    const int lane = tid & 31;
    const int cb   = tid >> 5;              // 0..7

    #pragma unroll
    for (int i = 0; i < 8; i++) {
        const int c = i * 8 + cb;
        const float4 v = __ldcs((const float4*)(xin + (size_t)c * HW_ + s0) + lane);
        const unsigned int u0 = h2_as_u(__floats2half2_rn(v.x, v.y));
        const unsigned int u1 = h2_as_u(__floats2half2_rn(v.z, v.w));
        const int w0 = c * 64 + lane * 2;
        const int ws = w0 ^ (((c >> 3) & 7) << 2);   // keeps 8B alignment
        *(uint2*)&smw[ws] = make_uint2(u0, u1);
    }
    __syncthreads();

    uint4* ob = (uint4*)(g_xt + ((size_t)n * HW_ + s0) * C_);
    #pragma unroll
    for (int j = 0; j < 2; j++) {
        const int u  = tid + 256 * j;       // 0..511
        const int p2 = (u >> 3) * 2;        // even pixel 0..126
        const int c8 = u & 7;               // channel-octet index
        const int c0 = c8 * 8;
        const int sw = c8 << 2;

        unsigned int w8[8];
        #pragma unroll
        for (int jj = 0; jj < 8; jj++) {
            const int w = (c0 + jj) * 64 + (p2 >> 1);
            w8[jj] = smw[w ^ sw];
        }
        uint4 lo, hi;
        lo.x = __byte_perm(w8[0], w8[1], 0x5410);
        lo.y = __byte_perm(w8[2], w8[3], 0x5410);
        lo.z = __byte_perm(w8[4], w8[5], 0x5410);
        lo.w = __byte_perm(w8[6], w8[7], 0x5410);
        hi.x = __byte_perm(w8[0], w8[1], 0x7632);
        hi.y = __byte_perm(w8[2], w8[3], 0x7632);
        hi.z = __byte_perm(w8[4], w8[5], 0x7632);
        hi.w = __byte_perm(w8[6], w8[7], 0x7632);

        ob[p2 * 8 + c8]       = lo;
        ob[(p2 + 1) * 8 + c8] = hi;
    }
}

// -------------------------------------------------------------------------
// Kernel 2: bilinear grid sample from NHWC fp16 scratch.
// 128 pixels per 256-thread block (16 per warp, 4 gather groups) — halves
// the number of blocks/barriers/grid-load chains vs the 64-px version.
// Phase A (warp-local): lanes 0..15 compute coords/weights for the warp's
// 16 pixels -> smem; __syncwarp only.
// Phase B: per group, 4 pixels per LDG.128 corner load; HFMA2 fp16 blend;
// conflict-free half2 staging.
// Phase C: half2 smem -> float4 coalesced streaming NCHW store
// (one warp stores 32 consecutive float4 = 512B run per channel).
// -------------------------------------------------------------------------
__global__ __launch_bounds__(256, 5) void grid_sample_kernel(
    const float* __restrict__ grid, float* __restrict__ out) {
    __shared__ int4         soff[128];       // byte offsets of 4 corners
    __shared__ uint4        swq[128];        // 4 weights as half2 (w,w)
    __shared__ unsigned int smq[128 * 33];   // [pixel][chpair] half2 staging

    const int bid     = blockIdx.x;
    const int wo_base = (bid & 1) * 128;     // 2 tiles per row
    const int ho      = (bid >> 1) & (HO_ - 1);
    const int n       = bid >> 9;            // 2*256 blocks per image

    const int tid  = threadIdx.x;
    const int warp = tid >> 5;
    const int lane = tid & 31;

    // Phase A: warp-local coordinate setup (pixels warp*16 .. warp*16+15).
    if (lane < 16) {
        const int p = warp * 16 + lane;
        const float2* gp =
            (const float2*)(grid + (((size_t)n * HO_ + ho) * WO_ + wo_base) * 2);
        const float2 g = __ldcs(&gp[p]);

        const float ix = (g.x + 1.0f) * 0.5f * (float)(W_ - 1);
        const float iy = (g.y + 1.0f) * 0.5f * (float)(H_ - 1);

        const float x0f = floorf(ix);
        const float y0f = floorf(iy);
        const float wx1 = ix - x0f;
        const float wy1 = iy - y0f;
        const float wx0 = 1.0f - wx1;
        const float wy0 = 1.0f - wy1;

        const int xi = (int)x0f;
        const int yi = (int)y0f;
        const int x0 = min(max(xi,     0), W_ - 1);
        const int x1 = min(max(xi + 1, 0), W_ - 1);
        const int y0 = min(max(yi,     0), H_ - 1);
        const int y1 = min(max(yi + 1, 0), H_ - 1);

        int4 o;                                   // BYTE offsets (row = 128B)
        o.x = (y0 * W_ + x0) * (C_ * 2);
        o.y = (y0 * W_ + x1) * (C_ * 2);
        o.z = (y1 * W_ + x0) * (C_ * 2);
        o.w = (y1 * W_ + x1) * (C_ * 2);
        soff[p] = o;

        uint4 wq;
        wq.x = h2_as_u(__float2half2_rn(wy0 * wx0));
        wq.y = h2_as_u(__float2half2_rn(wy0 * wx1));
        wq.z = h2_as_u(__float2half2_rn(wy1 * wx0));
        wq.w = h2_as_u(__float2half2_rn(wy1 * wx1));
        swq[p] = wq;
    }
    __syncwarp();      // warp-local: this warp only reads entries it wrote

    const char* xb = (const char*)(g_xt + (size_t)n * ((size_t)HW_ * C_));
    const int psel = lane >> 3;     // which of 4 pixels this lane serves
    const int sub  = lane & 7;      // 16B chunk within the 128B channel row
    const int sb   = sub * 16;

    #pragma unroll
    for (int g = 0; g < 4; g++) {
        const int p = warp * 16 + g * 4 + psel;
        const int4  o  = soff[p];   // LDS.128 (4 distinct addrs, bcast x8)
        const uint4 wq = swq[p];    // LDS.128

        // One LDG.128 per corner serves 4 pixels (512B across 4x128B rows).
        const uint4 v00 = *(const uint4*)(xb + o.x + sb);
        const uint4 v01 = *(const uint4*)(xb + o.y + sb);
        const uint4 v10 = *(const uint4*)(xb + o.z + sb);
        const uint4 v11 = *(const uint4*)(xb + o.w + sb);

        const __half2 w00 = u_as_h2(wq.x);
        const __half2 w01 = u_as_h2(wq.y);
        const __half2 w10 = u_as_h2(wq.z);
        const __half2 w11 = u_as_h2(wq.w);

        unsigned int r[4];
        {
            __half2 a;
            a = __hmul2(u_as_h2(v00.x), w00);
            a = __hfma2(u_as_h2(v01.x), w01, a);
            a = __hfma2(u_as_h2(v10.x), w10, a);
            a = __hfma2(u_as_h2(v11.x), w11, a);
            r[0] = h2_as_u(a);
            a = __hmul2(u_as_h2(v00.y), w00);
            a = __hfma2(u_as_h2(v01.y), w01, a);
            a = __hfma2(u_as_h2(v10.y), w10, a);
            a = __hfma2(u_as_h2(v11.y), w11, a);
            r[1] = h2_as_u(a);
            a = __hmul2(u_as_h2(v00.z), w00);
            a = __hfma2(u_as_h2(v01.z), w01, a);
            a = __hfma2(u_as_h2(v10.z), w10, a);
            a = __hfma2(u_as_h2(v11.z), w11, a);
            r[2] = h2_as_u(a);
            a = __hmul2(u_as_h2(v00.w), w00);
            a = __hfma2(u_as_h2(v01.w), w01, a);
            a = __hfma2(u_as_h2(v10.w), w10, a);
            a = __hfma2(u_as_h2(v11.w), w11, a);
            r[3] = h2_as_u(a);
        }

        // Conflict-free: bank = (psel + sub*4 + k) mod 32 covers all lanes.
        #pragma unroll
        for (int k = 0; k < 4; k++)
            smq[p * 33 + sub * 4 + k] = r[k];
    }
    __syncthreads();

    // Phase C: NCHW store. Warp = one channel, 32 consecutive float4 (512B).
    float* obase = out + (size_t)n * (C_ * HO_ * WO_) + (size_t)ho * WO_ + wo_base;
    #pragma unroll
    for (int it = 0; it < 8; it++) {
        const int u  = tid + 256 * it;    // 0..2047
        const int c  = u >> 5;            // channel 0..63
        const int q  = u & 31;            // float4 chunk within 128 pixels
        const int cp = c >> 1;
        const int hi = c & 1;

        float4 v;
        {
            const __half2 h0 = u_as_h2(smq[(q * 4 + 0) * 33 + cp]);
            const __half2 h1 = u_as_h2(smq[(q * 4 + 1) * 33 + cp]);
            const __half2 h2 = u_as_h2(smq[(q * 4 + 2) * 33 + cp]);
            const __half2 h3 = u_as_h2(smq[(q * 4 + 3) * 33 + cp]);
            v.x = hi ? __high2float(h0) : __low2float(h0);
            v.y = hi ? __high2float(h1) : __low2float(h1);
            v.z = hi ? __high2float(h2) : __low2float(h2);
            v.w = hi ? __high2float(h3) : __low2float(h3);
        }
        __stcs((float4*)(obase + (size_t)c * (HO_ * WO_) + q * 4), v);
    }
}

extern "C" void kernel_launch(void* const* d_in, const int* in_sizes, int n_in,
                              void* d_out, int out_size) {
    const float* x    = (const float*)d_in[0];   // [N, C, H, W]
    const float* grid = (const float*)d_in[1];   // [N, HO, WO, 2]
    float* out        = (float*)d_out;           // [N, C, HO, WO]
    (void)in_sizes; (void)n_in; (void)out_size;

    // Kernel 1: NCHW fp32 -> NHWC fp16 (streaming reads, wide ops)
    dim3 tgrid(HW_ / 128, N_);      // (512, 8)
    nchw_to_nhwc_h<<<tgrid, 256>>>(x);

    // Kernel 2: gather (L2-resident scratch) + fp16 blend + streaming store
    const int nblocks = N_ * HO_ * (WO_ / 128);  // 4096
    grid_sample_kernel<<<nblocks, 256>>>(grid, out);
}

// round 15
// speedup vs baseline: 1.1010x; 1.1010x over previous
#include <cuda_runtime.h>
#include <cuda_fp16.h>

// Problem constants
#define N_   8
#define C_   64
#define H_   256
#define W_   256
#define HO_  256
#define WO_  256
#define HW_  (H_ * W_)

// NHWC fp16 scratch for all images (67 MB). No allocation.
__device__ __half g_xt[(size_t)N_ * HW_ * C_];

static __device__ __forceinline__ unsigned int h2_as_u(__half2 h) {
    return *reinterpret_cast<unsigned int*>(&h);
}
static __device__ __forceinline__ __half2 u_as_h2(unsigned int u) {
    return *reinterpret_cast<__half2*>(&u);
}

// Shared memory union: T and S staging never live in the same block.
union SmemU {
    unsigned int smw[64 * 64];              // T: [ch][pixpair] 16 KB
    struct {
        int4         soff[64];              // S: corner byte offsets
        uint4        swq[64];               // S: weights as half2
        unsigned int smq[64 * 33];          // S: half2 result staging
    } s;
};

// -------------------------------------------------------------------------
// T body (R6, proven): 128 px x 64 ch of image n, NCHW fp32 -> NHWC fp16.
// -------------------------------------------------------------------------
static __device__ __forceinline__ void t_chunk(const float* __restrict__ x,
                                               int n, int tb, SmemU* u, int tid) {
    const int s0  = tb * 128;
    const float* xin = x + (size_t)n * (C_ * HW_);
    const int lane = tid & 31;
    const int cb   = tid >> 5;

    #pragma unroll
    for (int i = 0; i < 8; i++) {
        const int c = i * 8 + cb;
        const float4 v = __ldcs((const float4*)(xin + (size_t)c * HW_ + s0) + lane);
        const unsigned int u0 = h2_as_u(__floats2half2_rn(v.x, v.y));
        const unsigned int u1 = h2_as_u(__floats2half2_rn(v.z, v.w));
        const int w0 = c * 64 + lane * 2;
        const int ws = w0 ^ (((c >> 3) & 7) << 2);
        *(uint2*)&u->smw[ws] = make_uint2(u0, u1);
    }
    __syncthreads();

    uint4* ob = (uint4*)(g_xt + ((size_t)n * HW_ + s0) * C_);
    #pragma unroll
    for (int j = 0; j < 2; j++) {
        const int uu = tid + 256 * j;
        const int p2 = (uu >> 3) * 2;
        const int c8 = uu & 7;
        const int c0 = c8 * 8;
        const int sw = c8 << 2;

        unsigned int w8[8];
        #pragma unroll
        for (int jj = 0; jj < 8; jj++) {
            const int w = (c0 + jj) * 64 + (p2 >> 1);
            w8[jj] = u->smw[w ^ sw];
        }
        uint4 lo, hi;
        lo.x = __byte_perm(w8[0], w8[1], 0x5410);
        lo.y = __byte_perm(w8[2], w8[3], 0x5410);
        lo.z = __byte_perm(w8[4], w8[5], 0x5410);
        lo.w = __byte_perm(w8[6], w8[7], 0x5410);
        hi.x = __byte_perm(w8[0], w8[1], 0x7632);
        hi.y = __byte_perm(w8[2], w8[3], 0x7632);
        hi.z = __byte_perm(w8[4], w8[5], 0x7632);
        hi.w = __byte_perm(w8[6], w8[7], 0x7632);

        ob[p2 * 8 + c8]       = lo;
        ob[(p2 + 1) * 8 + c8] = hi;
    }
}

// -------------------------------------------------------------------------
// S body (R11, proven): 64 output pixels of one (n, ho) row.
// -------------------------------------------------------------------------
static __device__ __forceinline__ void s_chunk(const float* __restrict__ grid,
                                               float* __restrict__ out,
                                               int n, int sbi, SmemU* u, int tid) {
    const int wo_base = (sbi & 3) * 64;
    const int ho      = sbi >> 2;
    const int warp = tid >> 5;
    const int lane = tid & 31;

    // Phase A: warp-local coordinate setup (pixels warp*8 .. warp*8+7).
    if (lane < 8) {
        const int p = warp * 8 + lane;
        const float2* gp =
            (const float2*)(grid + (((size_t)n * HO_ + ho) * WO_ + wo_base) * 2);
        const float2 g = __ldcs(&gp[p]);

        const float ix = (g.x + 1.0f) * 0.5f * (float)(W_ - 1);
        const float iy = (g.y + 1.0f) * 0.5f * (float)(H_ - 1);

        const float x0f = floorf(ix);
        const float y0f = floorf(iy);
        const float wx1 = ix - x0f;
        const float wy1 = iy - y0f;
        const float wx0 = 1.0f - wx1;
        const float wy0 = 1.0f - wy1;

        const int xi = (int)x0f;
        const int yi = (int)y0f;
        const int x0 = min(max(xi,     0), W_ - 1);
        const int x1 = min(max(xi + 1, 0), W_ - 1);
        const int y0 = min(max(yi,     0), H_ - 1);
        const int y1 = min(max(yi + 1, 0), H_ - 1);

        int4 o;                                   // byte offsets (row = 128B)
        o.x = (y0 * W_ + x0) * (C_ * 2);
        o.y = (y0 * W_ + x1) * (C_ * 2);
        o.z = (y1 * W_ + x0) * (C_ * 2);
        o.w = (y1 * W_ + x1) * (C_ * 2);
        u->s.soff[p] = o;

        uint4 wq;
        wq.x = h2_as_u(__float2half2_rn(wy0 * wx0));
        wq.y = h2_as_u(__float2half2_rn(wy0 * wx1));
        wq.z = h2_as_u(__float2half2_rn(wy1 * wx0));
        wq.w = h2_as_u(__float2half2_rn(wy1 * wx1));
        u->s.swq[p] = wq;
    }
    __syncwarp();

    const char* xb = (const char*)(g_xt + (size_t)n * ((size_t)HW_ * C_));
    const int psel = lane >> 3;
    const int sub  = lane & 7;
    const int sb   = sub * 16;

    #pragma unroll
    for (int g = 0; g < 2; g++) {
        const int p = warp * 8 + g * 4 + psel;
        const int4  o  = u->s.soff[p];
        const uint4 wq = u->s.swq[p];

        const uint4 v00 = *(const uint4*)(xb + o.x + sb);
        const uint4 v01 = *(const uint4*)(xb + o.y + sb);
        const uint4 v10 = *(const uint4*)(xb + o.z + sb);
        const uint4 v11 = *(const uint4*)(xb + o.w + sb);

        const __half2 w00 = u_as_h2(wq.x);
        const __half2 w01 = u_as_h2(wq.y);
        const __half2 w10 = u_as_h2(wq.z);
        const __half2 w11 = u_as_h2(wq.w);

        unsigned int r[4];
        {
            __half2 a;
            a = __hmul2(u_as_h2(v00.x), w00);
            a = __hfma2(u_as_h2(v01.x), w01, a);
            a = __hfma2(u_as_h2(v10.x), w10, a);
            a = __hfma2(u_as_h2(v11.x), w11, a);
            r[0] = h2_as_u(a);
            a = __hmul2(u_as_h2(v00.y), w00);
            a = __hfma2(u_as_h2(v01.y), w01, a);
            a = __hfma2(u_as_h2(v10.y), w10, a);
            a = __hfma2(u_as_h2(v11.y), w11, a);
            r[1] = h2_as_u(a);
            a = __hmul2(u_as_h2(v00.z), w00);
            a = __hfma2(u_as_h2(v01.z), w01, a);
            a = __hfma2(u_as_h2(v10.z), w10, a);
            a = __hfma2(u_as_h2(v11.z), w11, a);
            r[2] = h2_as_u(a);
            a = __hmul2(u_as_h2(v00.w), w00);
            a = __hfma2(u_as_h2(v01.w), w01, a);
            a = __hfma2(u_as_h2(v10.w), w10, a);
            a = __hfma2(u_as_h2(v11.w), w11, a);
            r[3] = h2_as_u(a);
        }
        #pragma unroll
        for (int k = 0; k < 4; k++)
            u->s.smq[p * 33 + sub * 4 + k] = r[k];
    }
    __syncthreads();

    float* obase = out + (size_t)n * (C_ * HO_ * WO_) + (size_t)ho * WO_ + wo_base;
    #pragma unroll
    for (int it = 0; it < 4; it++) {
        const int uu = tid + 256 * it;
        const int c  = uu >> 4;
        const int q  = uu & 15;
        const int cp = c >> 1;
        const int hi = c & 1;

        float4 v;
        {
            const __half2 h0 = u_as_h2(u->s.smq[(q * 4 + 0) * 33 + cp]);
            const __half2 h1 = u_as_h2(u->s.smq[(q * 4 + 1) * 33 + cp]);
            const __half2 h2 = u_as_h2(u->s.smq[(q * 4 + 2) * 33 + cp]);
            const __half2 h3 = u_as_h2(u->s.smq[(q * 4 + 3) * 33 + cp]);
            v.x = hi ? __high2float(h0) : __low2float(h0);
            v.y = hi ? __high2float(h1) : __low2float(h1);
            v.z = hi ? __high2float(h2) : __low2float(h2);
            v.w = hi ? __high2float(h3) : __low2float(h3);
        }
        __stcs((float4*)(obase + (size_t)c * (HO_ * WO_) + q * 4), v);
    }
}

// -------------------------------------------------------------------------
// K1: pure transpose of images [n0, n0+cnt). blockIdx: (512, cnt).
// -------------------------------------------------------------------------
__global__ __launch_bounds__(256, 5) void t_kernel(const float* __restrict__ x,
                                                   int n0) {
    __shared__ SmemU u;
    t_chunk(x, n0 + blockIdx.y, blockIdx.x, &u, threadIdx.x);
}

// -------------------------------------------------------------------------
// K2: mixed. 6144 blocks: bid%3==0 -> T(img 4..7), else S(img 0..3).
// S deps (T0..T3) completed at the K1 launch boundary — no sync needed.
// -------------------------------------------------------------------------
__global__ __launch_bounds__(256, 5) void mixed_kernel(
    const float* __restrict__ x, const float* __restrict__ grid,
    float* __restrict__ out) {
    __shared__ SmemU u;
    const int bid = blockIdx.x;
    const int tid = threadIdx.x;
    const int m   = bid % 3;
    const int d   = bid / 3;

    if (m == 0) {                         // 2048 T blocks: images 4..7
        const int img = 4 + (d >> 9);
        t_chunk(x, img, d & 511, &u, tid);
    } else {                              // 4096 S blocks: images 0..3
        const int sidx = d * 2 + (m - 1); // 0..4095
        const int img  = sidx >> 10;
        s_chunk(grid, out, img, sidx & 1023, &u, tid);
    }
}

// -------------------------------------------------------------------------
// K3: pure sample of images [n0, n0+cnt). blockIdx: (1024, cnt).
// -------------------------------------------------------------------------
__global__ __launch_bounds__(256, 5) void s_kernel(
    const float* __restrict__ grid, float* __restrict__ out, int n0) {
    __shared__ SmemU u;
    s_chunk(grid, out, n0 + blockIdx.y, blockIdx.x, &u, threadIdx.x);
}

extern "C" void kernel_launch(void* const* d_in, const int* in_sizes, int n_in,
                              void* d_out, int out_size) {
    const float* x    = (const float*)d_in[0];   // [N, C, H, W]
    const float* grid = (const float*)d_in[1];   // [N, HO, WO, 2]
    float* out        = (float*)d_out;           // [N, C, HO, WO]
    (void)in_sizes; (void)n_in; (void)out_size;

    // K1: transpose images 0..3
    t_kernel<<<dim3(512, 4), 256>>>(x, 0);
    // K2: transpose images 4..7 overlapped with sampling images 0..3
    mixed_kernel<<<6144, 256>>>(x, grid, out);
    // K3: sample images 4..7
    s_kernel<<<dim3(1024, 4), 256>>>(grid, out, 4);
}